// round 9
// baseline (speedup 1.0000x reference)
#include <cuda_runtime.h>
#include <cstdint>

#define Nn      6144
#define Dd      256
#define KP      300
#define NT      17
#define NSLOT   (KP * NT)          // 5100
#define NSUB    17                 // sub-slices per type
#define NCTA2   289                // 17 types * 17 sub-slices (<=296 resident)
#define SLOTS   18                 // padded partial slots per (type,col)
#define ROWCAP2 28
#define ITERS   30
#define INVTAU  20.0f              // 1/0.05
#define DUMMY_MASS 1044.0f         // N - n_slots
#define STHREADS 512

#define DEV_NEG_INF (__int_as_float(0xff800000))

typedef unsigned long long u64;

// ---------------- device scratch (no runtime allocation) ------------------
__device__ float    g_h[(size_t)Nn * Dd];
__device__ float    g_hnorm[Nn];
__device__ float    g_pnorm[512];
__device__ float    g_M[(size_t)Nn * KP];          // rows in sorted-by-type order
__device__ int      g_perm[Nn];                    // sorted idx -> original row
__device__ int      g_tstart[NT + 1];
__device__ float2   g_cpart[2][(size_t)NT * KP * SLOTS];
__device__ float2   g_upart[2][NCTA2];
__device__ unsigned g_flag[NCTA2];

// ---------------- helpers --------------------------------------------------
__device__ __forceinline__ float wred_max(float m) {
#pragma unroll
    for (int o = 16; o; o >>= 1) m = fmaxf(m, __shfl_xor_sync(0xffffffffu, m, o));
    return m;
}
__device__ __forceinline__ float wred_sum(float s) {
#pragma unroll
    for (int o = 16; o; o >>= 1) s += __shfl_xor_sync(0xffffffffu, s, o);
    return s;
}
__device__ __forceinline__ u64 pk2(float lo, float hi) {
    u64 r; asm("mov.b64 %0,{%1,%2};" : "=l"(r) : "f"(lo), "f"(hi)); return r;
}
__device__ __forceinline__ void upk2(u64 v, float& lo, float& hi) {
    asm("mov.b64 {%0,%1},%2;" : "=f"(lo), "=f"(hi) : "l"(v));
}
__device__ __forceinline__ void ffma2(u64& d, u64 a, u64 b) {
    asm("fma.rn.f32x2 %0,%1,%2,%0;" : "+l"(d) : "l"(a), "l"(b));
}
// running log-sum-exp combine of partial (mq, sq) into (m, s)
__device__ __forceinline__ void lse_comb(float& m, float& s, float mq, float sq) {
    if (sq > 0.f) {
        if (mq <= m) s += sq * __expf(mq - m);
        else { s = s * __expf(m - mq) + sq; m = mq; }
    }
}

// ---------------- GEMM 1: h = selu(emb @ W1 + b1) --------------------------
__global__ __launch_bounds__(256) void gemm_h_kernel(
    const float* __restrict__ A, const float* __restrict__ B,
    const float* __restrict__ bias)
{
    __shared__ float As[8][128];
    __shared__ float Bs[8][128];
    int tid = threadIdx.x;
    int rb = blockIdx.y * 128;
    int cb = blockIdx.x * 128;
    int tx = tid & 15, ty = tid >> 4;
    u64 acc2[8][4];
#pragma unroll
    for (int i = 0; i < 8; ++i)
#pragma unroll
        for (int j = 0; j < 4; ++j) acc2[i][j] = 0ull;

    int am = tid >> 1, ak = (tid & 1) * 4;
    int bk = tid >> 5, bn = (tid & 31) * 4;

    for (int k0 = 0; k0 < Dd; k0 += 8) {
        float4 a4 = *(const float4*)(A + (size_t)(rb + am) * Dd + k0 + ak);
        float4 b4 = *(const float4*)(B + (size_t)(k0 + bk) * Dd + cb + bn);
        __syncthreads();
        As[ak + 0][am] = a4.x; As[ak + 1][am] = a4.y;
        As[ak + 2][am] = a4.z; As[ak + 3][am] = a4.w;
        *(float4*)&Bs[bk][bn] = b4;
        __syncthreads();
#pragma unroll
        for (int k = 0; k < 8; ++k) {
            float4 a0 = *(const float4*)&As[k][ty * 8];
            float4 a1 = *(const float4*)&As[k][ty * 8 + 4];
            float4 b0 = *(const float4*)&Bs[k][tx * 8];
            float4 b1 = *(const float4*)&Bs[k][tx * 8 + 4];
            u64 bv[4] = {pk2(b0.x, b0.y), pk2(b0.z, b0.w),
                         pk2(b1.x, b1.y), pk2(b1.z, b1.w)};
            float av[8] = {a0.x, a0.y, a0.z, a0.w, a1.x, a1.y, a1.z, a1.w};
#pragma unroll
            for (int i = 0; i < 8; ++i) {
                u64 a2 = pk2(av[i], av[i]);
#pragma unroll
                for (int j = 0; j < 4; ++j) ffma2(acc2[i][j], a2, bv[j]);
            }
        }
    }
    const float SC = 1.0507009873554805f, AL = 1.6732632423543772f;
#pragma unroll
    for (int i = 0; i < 8; ++i) {
        int row = rb + ty * 8 + i;
        float o[8];
#pragma unroll
        for (int j = 0; j < 4; ++j) upk2(acc2[i][j], o[2 * j], o[2 * j + 1]);
#pragma unroll
        for (int j = 0; j < 8; ++j) {
            float vv = o[j] + bias[cb + tx * 8 + j];
            o[j] = (vv > 0.f) ? SC * vv : SC * AL * expm1f(vv);
        }
        *(float4*)(g_h + (size_t)row * Dd + cb + tx * 8)     = make_float4(o[0], o[1], o[2], o[3]);
        *(float4*)(g_h + (size_t)row * Dd + cb + tx * 8 + 4) = make_float4(o[4], o[5], o[6], o[7]);
    }
}

// ----- norms (768 h CTAs + 48 pnorm CTAs) + sort (last CTA) ----------------
__global__ void normsort_kernel(const float* __restrict__ P,
                                const int* __restrict__ jt)
{
    int bid = blockIdx.x;
    int tid = threadIdx.x;

    if (bid == Nn / 8 + 48) {
        __shared__ int hist[NT][256];
        __shared__ int tstart_s[NT + 1];
        for (int i = tid; i < NCTA2; i += 256) g_flag[i] = 0;

        int cnt[NT];
#pragma unroll
        for (int t = 0; t < NT; ++t) cnt[t] = 0;
        const int CH = Nn / 256;             // 24
        int s0 = tid * CH;
        for (int i = 0; i < CH; ++i) cnt[jt[s0 + i]]++;
#pragma unroll
        for (int t = 0; t < NT; ++t) hist[t][tid] = cnt[t];
        __syncthreads();

        int v[NT];
#pragma unroll
        for (int t = 0; t < NT; ++t) v[t] = cnt[t];
        for (int off = 1; off < 256; off <<= 1) {
            int a[NT];
#pragma unroll
            for (int t = 0; t < NT; ++t) a[t] = (tid >= off) ? hist[t][tid - off] : 0;
            __syncthreads();
#pragma unroll
            for (int t = 0; t < NT; ++t) { v[t] += a[t]; hist[t][tid] = v[t]; }
            __syncthreads();
        }
        if (tid == 0) {
            int s = 0;
            for (int t = 0; t < NT; ++t) {
                tstart_s[t] = s; g_tstart[t] = s; s += hist[t][255];
            }
            tstart_s[NT] = s; g_tstart[NT] = s;
        }
        __syncthreads();
        int ofs[NT];
#pragma unroll
        for (int t = 0; t < NT; ++t) ofs[t] = tstart_s[t] + v[t] - cnt[t];
        for (int i = 0; i < CH; ++i) {
            int ty = jt[s0 + i];
            g_perm[ofs[ty]++] = s0 + i;
        }
        return;
    }

    int w = tid >> 5, lane = tid & 31;
    const float* src;
    float* dst;
    if (bid < Nn / 8) {
        int row = bid * 8 + w;
        src = g_h + (size_t)row * Dd;
        dst = g_hnorm + row;
    } else {
        int row = (bid - Nn / 8) * 8 + w;
        if (row >= 384) return;
        src = P + (size_t)row * Dd;
        dst = g_pnorm + row;
    }
    const float4* x = (const float4*)src;
    float s = 0.f;
#pragma unroll
    for (int i = 0; i < 2; ++i) {
        float4 v = x[lane + 32 * i];
        s += v.x * v.x + v.y * v.y + v.z * v.z + v.w * v.w;
    }
    s = wred_sum(s);
    if (lane == 0) *dst = s;
}

// ---- GEMM 2: M_sorted[i][j] = -max(0,|h|^2+|p|^2-2h.p)/tau ----------------
__global__ __launch_bounds__(256) void gemm_M_kernel(const float* __restrict__ P)
{
    __shared__ float As[8][128];
    __shared__ float Bs[8][128];
    __shared__ int prow[128];
    int tid = threadIdx.x;
    int rb = blockIdx.y * 128;
    int cb = blockIdx.x * 128;
    int tx = tid & 15, ty = tid >> 4;
    if (tid < 128) prow[tid] = g_perm[rb + tid];
    __syncthreads();

    u64 acc2[8][4];
#pragma unroll
    for (int i = 0; i < 8; ++i)
#pragma unroll
        for (int j = 0; j < 4; ++j) acc2[i][j] = 0ull;

    int am = tid >> 1, ak = (tid & 1) * 4;
    int bc = tid >> 1, bk = (tid & 1) * 4;
    int arow = prow[am];

    for (int k0 = 0; k0 < Dd; k0 += 8) {
        float4 a4 = *(const float4*)(g_h + (size_t)arow * Dd + k0 + ak);
        float4 b4 = *(const float4*)(P + (size_t)(cb + bc) * Dd + k0 + bk);
        __syncthreads();
        As[ak + 0][am] = a4.x; As[ak + 1][am] = a4.y;
        As[ak + 2][am] = a4.z; As[ak + 3][am] = a4.w;
        Bs[bk + 0][bc] = b4.x; Bs[bk + 1][bc] = b4.y;
        Bs[bk + 2][bc] = b4.z; Bs[bk + 3][bc] = b4.w;
        __syncthreads();
#pragma unroll
        for (int k = 0; k < 8; ++k) {
            float4 a0 = *(const float4*)&As[k][ty * 8];
            float4 a1 = *(const float4*)&As[k][ty * 8 + 4];
            float4 b0 = *(const float4*)&Bs[k][tx * 8];
            float4 b1 = *(const float4*)&Bs[k][tx * 8 + 4];
            u64 bv[4] = {pk2(b0.x, b0.y), pk2(b0.z, b0.w),
                         pk2(b1.x, b1.y), pk2(b1.z, b1.w)};
            float av[8] = {a0.x, a0.y, a0.z, a0.w, a1.x, a1.y, a1.z, a1.w};
#pragma unroll
            for (int i = 0; i < 8; ++i) {
                u64 a2 = pk2(av[i], av[i]);
#pragma unroll
                for (int j = 0; j < 4; ++j) ffma2(acc2[i][j], a2, bv[j]);
            }
        }
    }
#pragma unroll
    for (int i = 0; i < 8; ++i) {
        int srow = rb + ty * 8 + i;
        float hn = g_hnorm[prow[ty * 8 + i]];
        float o[8];
#pragma unroll
        for (int j = 0; j < 4; ++j) upk2(acc2[i][j], o[2 * j], o[2 * j + 1]);
#pragma unroll
        for (int j = 0; j < 8; ++j) {
            int col = cb + tx * 8 + j;
            if (col < KP) {
                float d2 = fmaxf(hn + g_pnorm[col] - 2.0f * o[j], 0.0f);
                g_M[(size_t)srow * KP + col] = -d2 * INVTAU;
            }
        }
    }
}

// ---------------- grid barrier (289 CTAs) ----------------------------------
__device__ __forceinline__ void grid_barrier(int epoch)
{
    int tid = threadIdx.x;
    __threadfence();
    __syncthreads();
    if (tid == 0) atomicExch(&g_flag[blockIdx.x], (unsigned)epoch);
    if (tid < NCTA2) {
        volatile unsigned* vf = g_flag;
        while (vf[tid] < (unsigned)epoch) { }
    }
    __threadfence();
    __syncthreads();
}

// ====== persistent Sinkhorn: 289 CTAs x 512 thr, 2 CTAs/SM =================
__global__ __launch_bounds__(STHREADS, 2) void sinkhorn_kernel(
    float* __restrict__ out_logits, float* __restrict__ out_T)
{
    extern __shared__ float sm[];
    float* Ms   = sm;                        // ROWCAP2*KP
    float* Vs   = sm + ROWCAP2 * KP;         // KP
    float* logu = Vs + KP + 4;               // ROWCAP2
    __shared__ float vlast_s;

    int c = blockIdx.x;
    int t = c / NSUB, sub = c - t * NSUB;
    int tid = threadIdx.x, w = tid >> 5, l = tid & 31;
    int gs = g_tstart[t], ge = g_tstart[t + 1], len = ge - gs;
    int r0 = gs + (sub * len) / NSUB;
    int r1 = gs + ((sub + 1) * len) / NSUB;
    int rows = r1 - r0;
    if (rows > ROWCAP2) rows = ROWCAP2;

    {   // vectorized tile load (rows*75 float4s, 16B-aligned base)
        const float4* src = (const float4*)(g_M + (size_t)r0 * KP);
        float4* dst = (float4*)Ms;
        int n4 = rows * (KP / 4);
        for (int e = tid; e < n4; e += STHREADS) dst[e] = src[e];
    }
    __syncthreads();

    for (int it = 1; it <= ITERS + 1; ++it) {
        // -------- Phase A: combine 17 column partials -> V -----------------
        if (it == 1) {
            for (int j = tid; j < KP; j += STHREADS) Vs[j] = 0.f;
            if (tid == 0) vlast_s = 0.f;
        } else {
            int pp = (it - 1) & 1;
            for (int j = tid; j < KP; j += STHREADS) {
                const float4* p4 =
                    (const float4*)&g_cpart[pp][(size_t)(t * KP + j) * SLOTS];
                float m = DEV_NEG_INF, s = 0.f;
#pragma unroll
                for (int a = 0; a < 8; ++a) {
                    float4 q = __ldcg(p4 + a);
                    lse_comb(m, s, q.x, q.y);
                    lse_comb(m, s, q.z, q.w);
                }
                float4 q8 = __ldcg(p4 + 8);       // slot 16 (17th partial)
                lse_comb(m, s, q8.x, q8.y);
                Vs[j] = -(m + logf(s));
            }
            if (tid < 32) {
                float m = DEV_NEG_INF, s = 0.f;
#pragma unroll
                for (int q = 0; q < 10; ++q) {
                    int i = l + 32 * q;
                    if (i < NCTA2) {
                        float2 up = __ldcg(&g_upart[pp][i]);
                        lse_comb(m, s, up.x, up.y);
                    }
                }
                // warp-combine the 32 running pairs
#pragma unroll
                for (int o = 16; o; o >>= 1) {
                    float mo = __shfl_xor_sync(0xffffffffu, m, o);
                    float so = __shfl_xor_sync(0xffffffffu, s, o);
                    lse_comb(m, s, mo, so);
                }
                if (l == 0) vlast_s = logf(DUMMY_MASS) - (m + logf(s));
            }
        }
        __syncthreads();
        float vlast = vlast_s;
        if (it == ITERS + 1) break;           // V holds v after 30 iters

        // -------- Phase B: row LSE -> log_u (single pass, reg cache) -------
        for (int i = w; i < rows; i += STHREADS / 32) {
            const float* mr = Ms + i * KP;
            float r[10];
#pragma unroll
            for (int q = 0; q < 10; ++q) {
                int j = l + 32 * q;
                r[q] = (j < KP) ? mr[j] + Vs[j] : DEV_NEG_INF;
            }
            float m1 = vlast;
#pragma unroll
            for (int q = 0; q < 10; ++q) m1 = fmaxf(m1, r[q]);
            m1 = wred_max(m1);
            float s = (l == 0) ? __expf(vlast - m1) : 0.f;
#pragma unroll
            for (int q = 0; q < 10; ++q) s += __expf(r[q] - m1);
            s = wred_sum(s);
            if (l == 0) logu[i] = -(m1 + logf(s));
        }
        __syncthreads();

        // -------- Phase C: column (max,sumexp) partials --------------------
        int pw = it & 1;
        for (int j = tid; j < KP; j += STHREADS) {
            float ma = DEV_NEG_INF, mb = DEV_NEG_INF;
            int i = 0;
            for (; i + 1 < rows; i += 2) {
                ma = fmaxf(ma, Ms[i * KP + j] + logu[i]);
                mb = fmaxf(mb, Ms[(i + 1) * KP + j] + logu[i + 1]);
            }
            if (i < rows) ma = fmaxf(ma, Ms[i * KP + j] + logu[i]);
            float m1 = fmaxf(ma, mb);
            float sa = 0.f, sb = 0.f;
            i = 0;
            for (; i + 1 < rows; i += 2) {
                sa += __expf(Ms[i * KP + j] + logu[i] - m1);
                sb += __expf(Ms[(i + 1) * KP + j] + logu[i + 1] - m1);
            }
            if (i < rows) sa += __expf(Ms[i * KP + j] + logu[i] - m1);
            __stcg(&g_cpart[pw][(size_t)(t * KP + j) * SLOTS + sub],
                   make_float2(m1, sa + sb));
        }
        if (tid < 32) {
            float m1 = DEV_NEG_INF;
            for (int i = l; i < rows; i += 32) m1 = fmaxf(m1, logu[i]);
            m1 = wred_max(m1);
            float s = 0.f;
            for (int i = l; i < rows; i += 32) s += __expf(logu[i] - m1);
            s = wred_sum(s);
            if (l == 0) __stcg(&g_upart[pw][c], make_float2(m1, s));
        }
        grid_barrier(it);
    }

    // -------- Epilogue: T nonzeros + logits --------------------------------
    for (int i = w; i < rows; i += STHREADS / 32) {
        int n = g_perm[r0 + i];
        float lu = logu[i];
        const float* mr = Ms + i * KP;
        float* Trow = out_T + (size_t)n * NSLOT + t;
        float* Lrow = out_logits + (size_t)n * KP;
        for (int j = l; j < KP; j += 32) {
            float val = __expf(mr[j] + lu + Vs[j]);
            Trow[j * NT] = val;
            Lrow[j] = logf(val + 1e-8f);
        }
    }
}

// ---------------- launch ----------------------------------------------------
extern "C" void kernel_launch(void* const* d_in, const int* in_sizes, int n_in,
                              void* d_out, int out_size)
{
    const float* emb   = (const float*)d_in[0];
    const float* W1    = (const float*)d_in[1];
    const float* b1    = (const float*)d_in[2];
    const float* proto = (const float*)d_in[3];
    const int*   jt    = (const int*)d_in[4];
    (void)in_sizes; (void)n_in; (void)out_size;

    float* logits = (float*)d_out;
    float* T      = logits + (size_t)Nn * KP;

    size_t smem = (size_t)(ROWCAP2 * KP + KP + 4 + ROWCAP2 + 8) * sizeof(float);
    cudaFuncSetAttribute(sinkhorn_kernel,
                         cudaFuncAttributeMaxDynamicSharedMemorySize, (int)smem);

    gemm_h_kernel<<<dim3(Dd / 128, Nn / 128), 256>>>(emb, W1, b1);
    normsort_kernel<<<Nn / 8 + 49, 256>>>(proto, jt);
    gemm_M_kernel<<<dim3(3, Nn / 128), 256>>>(proto);
    cudaMemsetAsync(T, 0, (size_t)Nn * NSLOT * sizeof(float));
    sinkhorn_kernel<<<NCTA2, STHREADS, smem>>>(logits, T);
}

// round 11
// speedup vs baseline: 1.5066x; 1.5066x over previous
#include <cuda_runtime.h>
#include <cstdint>

#define Nn      6144
#define Dd      256
#define KP      300
#define NT      17
#define NSLOT   (KP * NT)          // 5100
#define NCTA    136                // 17 types * 8 sub-slices
#define ROWCAP  64
#define ITERS   30
#define INVTAU  20.0f              // 1/0.05
#define DUMMY_MASS 1044.0f         // N - n_slots
#define STHREADS 512               // sinkhorn block size (16 warps)

#define DEV_NEG_INF (__int_as_float(0xff800000))

typedef unsigned long long u64;

// ---------------- device scratch (no runtime allocation) ------------------
__device__ float    g_h[(size_t)Nn * Dd];
__device__ float    g_hnorm[Nn];
__device__ float    g_pnorm[512];
__device__ float    g_M[(size_t)Nn * KP];          // rows in sorted-by-type order
__device__ int      g_perm[Nn];                    // sorted idx -> original row
__device__ int      g_tstart[NT + 1];
__device__ float2   g_cpart[2][NT * KP * 8];       // [parity][(t*KP+j)*8+sub]
__device__ float2   g_upart[2][NCTA];
__device__ unsigned g_flag[NCTA];

// ---------------- helpers --------------------------------------------------
__device__ __forceinline__ float wred_max(float m) {
#pragma unroll
    for (int o = 16; o; o >>= 1) m = fmaxf(m, __shfl_xor_sync(0xffffffffu, m, o));
    return m;
}
__device__ __forceinline__ float wred_sum(float s) {
#pragma unroll
    for (int o = 16; o; o >>= 1) s += __shfl_xor_sync(0xffffffffu, s, o);
    return s;
}
__device__ __forceinline__ u64 pk2(float lo, float hi) {
    u64 r; asm("mov.b64 %0,{%1,%2};" : "=l"(r) : "f"(lo), "f"(hi)); return r;
}
__device__ __forceinline__ void upk2(u64 v, float& lo, float& hi) {
    asm("mov.b64 {%0,%1},%2;" : "=f"(lo), "=f"(hi) : "l"(v));
}
__device__ __forceinline__ void ffma2(u64& d, u64 a, u64 b) {
    asm("fma.rn.f32x2 %0,%1,%2,%0;" : "+l"(d) : "l"(a), "l"(b));
}

// ---------------- GEMM 1: h = selu(emb @ W1 + b1) --------------------------
__global__ __launch_bounds__(256) void gemm_h_kernel(
    const float* __restrict__ A, const float* __restrict__ B,
    const float* __restrict__ bias)
{
    __shared__ float As[8][128];
    __shared__ float Bs[8][128];
    int tid = threadIdx.x;
    int rb = blockIdx.y * 128;
    int cb = blockIdx.x * 128;
    int tx = tid & 15, ty = tid >> 4;
    u64 acc2[8][4];
#pragma unroll
    for (int i = 0; i < 8; ++i)
#pragma unroll
        for (int j = 0; j < 4; ++j) acc2[i][j] = 0ull;

    int am = tid >> 1, ak = (tid & 1) * 4;
    int bk = tid >> 5, bn = (tid & 31) * 4;

    for (int k0 = 0; k0 < Dd; k0 += 8) {
        float4 a4 = *(const float4*)(A + (size_t)(rb + am) * Dd + k0 + ak);
        float4 b4 = *(const float4*)(B + (size_t)(k0 + bk) * Dd + cb + bn);
        __syncthreads();
        As[ak + 0][am] = a4.x; As[ak + 1][am] = a4.y;
        As[ak + 2][am] = a4.z; As[ak + 3][am] = a4.w;
        *(float4*)&Bs[bk][bn] = b4;
        __syncthreads();
#pragma unroll
        for (int k = 0; k < 8; ++k) {
            float4 a0 = *(const float4*)&As[k][ty * 8];
            float4 a1 = *(const float4*)&As[k][ty * 8 + 4];
            float4 b0 = *(const float4*)&Bs[k][tx * 8];
            float4 b1 = *(const float4*)&Bs[k][tx * 8 + 4];
            u64 bv[4] = {pk2(b0.x, b0.y), pk2(b0.z, b0.w),
                         pk2(b1.x, b1.y), pk2(b1.z, b1.w)};
            float av[8] = {a0.x, a0.y, a0.z, a0.w, a1.x, a1.y, a1.z, a1.w};
#pragma unroll
            for (int i = 0; i < 8; ++i) {
                u64 a2 = pk2(av[i], av[i]);
#pragma unroll
                for (int j = 0; j < 4; ++j) ffma2(acc2[i][j], a2, bv[j]);
            }
        }
    }
    const float SC = 1.0507009873554805f, AL = 1.6732632423543772f;
#pragma unroll
    for (int i = 0; i < 8; ++i) {
        int row = rb + ty * 8 + i;
        float o[8];
#pragma unroll
        for (int j = 0; j < 4; ++j) upk2(acc2[i][j], o[2 * j], o[2 * j + 1]);
#pragma unroll
        for (int j = 0; j < 8; ++j) {
            float vv = o[j] + bias[cb + tx * 8 + j];
            o[j] = (vv > 0.f) ? SC * vv : SC * AL * expm1f(vv);
        }
        *(float4*)(g_h + (size_t)row * Dd + cb + tx * 8)     = make_float4(o[0], o[1], o[2], o[3]);
        *(float4*)(g_h + (size_t)row * Dd + cb + tx * 8 + 4) = make_float4(o[4], o[5], o[6], o[7]);
    }
}

// ----- norms (768 h CTAs + 48 pnorm CTAs) + sort (last CTA) ----------------
__global__ void normsort_kernel(const float* __restrict__ P,
                                const int* __restrict__ jt)
{
    int bid = blockIdx.x;
    int tid = threadIdx.x;

    if (bid == Nn / 8 + 48) {
        __shared__ int hist[NT][256];
        __shared__ int tstart_s[NT + 1];
        if (tid < NCTA) g_flag[tid] = 0;     // reset barrier flags each replay

        int cnt[NT];
#pragma unroll
        for (int t = 0; t < NT; ++t) cnt[t] = 0;
        const int CH = Nn / 256;             // 24
        int s0 = tid * CH;
        for (int i = 0; i < CH; ++i) cnt[jt[s0 + i]]++;
#pragma unroll
        for (int t = 0; t < NT; ++t) hist[t][tid] = cnt[t];
        __syncthreads();

        int v[NT];
#pragma unroll
        for (int t = 0; t < NT; ++t) v[t] = cnt[t];
        for (int off = 1; off < 256; off <<= 1) {
            int a[NT];
#pragma unroll
            for (int t = 0; t < NT; ++t) a[t] = (tid >= off) ? hist[t][tid - off] : 0;
            __syncthreads();
#pragma unroll
            for (int t = 0; t < NT; ++t) { v[t] += a[t]; hist[t][tid] = v[t]; }
            __syncthreads();
        }
        if (tid == 0) {
            int s = 0;
            for (int t = 0; t < NT; ++t) {
                tstart_s[t] = s; g_tstart[t] = s; s += hist[t][255];
            }
            tstart_s[NT] = s; g_tstart[NT] = s;
        }
        __syncthreads();
        int ofs[NT];
#pragma unroll
        for (int t = 0; t < NT; ++t) ofs[t] = tstart_s[t] + v[t] - cnt[t];
        for (int i = 0; i < CH; ++i) {
            int ty = jt[s0 + i];
            g_perm[ofs[ty]++] = s0 + i;
        }
        return;
    }

    int w = tid >> 5, lane = tid & 31;
    const float* src;
    float* dst;
    if (bid < Nn / 8) {
        int row = bid * 8 + w;
        src = g_h + (size_t)row * Dd;
        dst = g_hnorm + row;
    } else {
        int row = (bid - Nn / 8) * 8 + w;
        if (row >= 384) return;
        src = P + (size_t)row * Dd;
        dst = g_pnorm + row;
    }
    const float4* x = (const float4*)src;
    float s = 0.f;
#pragma unroll
    for (int i = 0; i < 2; ++i) {
        float4 v = x[lane + 32 * i];
        s += v.x * v.x + v.y * v.y + v.z * v.z + v.w * v.w;
    }
    s = wred_sum(s);
    if (lane == 0) *dst = s;
}

// ---- GEMM 2: M_sorted[i][j] = -max(0,|h|^2+|p|^2-2h.p)/tau ----------------
__global__ __launch_bounds__(256) void gemm_M_kernel(const float* __restrict__ P)
{
    __shared__ float As[8][128];
    __shared__ float Bs[8][128];
    __shared__ int prow[128];
    int tid = threadIdx.x;
    int rb = blockIdx.y * 128;
    int cb = blockIdx.x * 128;
    int tx = tid & 15, ty = tid >> 4;
    if (tid < 128) prow[tid] = g_perm[rb + tid];
    __syncthreads();

    u64 acc2[8][4];
#pragma unroll
    for (int i = 0; i < 8; ++i)
#pragma unroll
        for (int j = 0; j < 4; ++j) acc2[i][j] = 0ull;

    int am = tid >> 1, ak = (tid & 1) * 4;
    int bc = tid >> 1, bk = (tid & 1) * 4;
    int arow = prow[am];

    for (int k0 = 0; k0 < Dd; k0 += 8) {
        float4 a4 = *(const float4*)(g_h + (size_t)arow * Dd + k0 + ak);
        float4 b4 = *(const float4*)(P + (size_t)(cb + bc) * Dd + k0 + bk);
        __syncthreads();
        As[ak + 0][am] = a4.x; As[ak + 1][am] = a4.y;
        As[ak + 2][am] = a4.z; As[ak + 3][am] = a4.w;
        Bs[bk + 0][bc] = b4.x; Bs[bk + 1][bc] = b4.y;
        Bs[bk + 2][bc] = b4.z; Bs[bk + 3][bc] = b4.w;
        __syncthreads();
#pragma unroll
        for (int k = 0; k < 8; ++k) {
            float4 a0 = *(const float4*)&As[k][ty * 8];
            float4 a1 = *(const float4*)&As[k][ty * 8 + 4];
            float4 b0 = *(const float4*)&Bs[k][tx * 8];
            float4 b1 = *(const float4*)&Bs[k][tx * 8 + 4];
            u64 bv[4] = {pk2(b0.x, b0.y), pk2(b0.z, b0.w),
                         pk2(b1.x, b1.y), pk2(b1.z, b1.w)};
            float av[8] = {a0.x, a0.y, a0.z, a0.w, a1.x, a1.y, a1.z, a1.w};
#pragma unroll
            for (int i = 0; i < 8; ++i) {
                u64 a2 = pk2(av[i], av[i]);
#pragma unroll
                for (int j = 0; j < 4; ++j) ffma2(acc2[i][j], a2, bv[j]);
            }
        }
    }
#pragma unroll
    for (int i = 0; i < 8; ++i) {
        int srow = rb + ty * 8 + i;
        float hn = g_hnorm[prow[ty * 8 + i]];
        float o[8];
#pragma unroll
        for (int j = 0; j < 4; ++j) upk2(acc2[i][j], o[2 * j], o[2 * j + 1]);
#pragma unroll
        for (int j = 0; j < 8; ++j) {
            int col = cb + tx * 8 + j;
            if (col < KP) {
                float d2 = fmaxf(hn + g_pnorm[col] - 2.0f * o[j], 0.0f);
                g_M[(size_t)srow * KP + col] = -d2 * INVTAU;
            }
        }
    }
}

// ---------------- grid barrier ---------------------------------------------
__device__ __forceinline__ void grid_barrier(int epoch)
{
    int tid = threadIdx.x;
    __threadfence();
    __syncthreads();
    if (tid == 0) atomicExch(&g_flag[blockIdx.x], (unsigned)epoch);
    if (tid < NCTA) {
        volatile unsigned* vf = g_flag;
        while (vf[tid] < (unsigned)epoch) { }
    }
    __threadfence();
    __syncthreads();
}

// ========== persistent Sinkhorn (136 CTAs x 512 thr) =======================
__global__ __launch_bounds__(STHREADS, 1) void sinkhorn_kernel(
    float* __restrict__ out_logits, float* __restrict__ out_T)
{
    extern __shared__ float sm[];
    float* Ms   = sm;                        // ROWCAP*KP
    float* Vs   = sm + ROWCAP * KP;          // KP
    float* logu = Vs + KP + 4;               // ROWCAP
    __shared__ float vlast_s;

    int c = blockIdx.x, t = c >> 3, sub = c & 7;
    int tid = threadIdx.x, w = tid >> 5, l = tid & 31;
    int gs = g_tstart[t], ge = g_tstart[t + 1], len = ge - gs;
    int r0 = gs + (sub * len) / 8;
    int r1 = gs + ((sub + 1) * len) / 8;
    int rows = r1 - r0;
    if (rows > ROWCAP) rows = ROWCAP;

    // vectorized tile load (rows*KP divisible by 4; base 16B aligned)
    {
        const float4* src = (const float4*)(g_M + (size_t)r0 * KP);
        float4* dst = (float4*)Ms;
        int n4 = rows * (KP / 4);
        for (int e = tid; e < n4; e += STHREADS) dst[e] = src[e];
    }
    __syncthreads();

    for (int it = 1; it <= ITERS + 1; ++it) {
        // -------- Phase A: combine previous column partials into V ---------
        if (it == 1) {
            for (int j = tid; j < KP; j += STHREADS) Vs[j] = 0.f;
            if (tid == 0) vlast_s = 0.f;
        } else {
            int pp = (it - 1) & 1;
            for (int j = tid; j < KP; j += STHREADS) {
                const float4* p4 = (const float4*)&g_cpart[pp][(t * KP + j) * 8];
                float4 q[4];
#pragma unroll
                for (int a = 0; a < 4; ++a) q[a] = __ldcg(p4 + a);
                float gm = DEV_NEG_INF;
#pragma unroll
                for (int a = 0; a < 4; ++a) {
                    gm = fmaxf(gm, q[a].x);
                    gm = fmaxf(gm, q[a].z);
                }
                float s = 0.f;
#pragma unroll
                for (int a = 0; a < 4; ++a) {
                    if (q[a].y > 0.f) s += q[a].y * __expf(q[a].x - gm);
                    if (q[a].w > 0.f) s += q[a].w * __expf(q[a].z - gm);
                }
                Vs[j] = -(gm + logf(s));
            }
            if (tid < 32) {
                float2 up[5];
                float gm = DEV_NEG_INF;
#pragma unroll
                for (int q = 0; q < 5; ++q) {
                    int i = l + 32 * q;
                    up[q] = (i < NCTA) ? __ldcg(&g_upart[pp][i])
                                       : make_float2(DEV_NEG_INF, 0.f);
                    gm = fmaxf(gm, up[q].x);
                }
                gm = wred_max(gm);
                float s = 0.f;
#pragma unroll
                for (int q = 0; q < 5; ++q)
                    if (up[q].y > 0.f) s += up[q].y * __expf(up[q].x - gm);
                s = wred_sum(s);
                if (l == 0) vlast_s = logf(DUMMY_MASS) - (gm + logf(s));
            }
        }
        __syncthreads();
        float vlast = vlast_s;
        if (it == ITERS + 1) break;           // V holds v after 30 iters

        // -------- Phase B: row LSE -> log_u (single pass, reg cache) -------
        for (int i = w; i < rows; i += STHREADS / 32) {
            const float* mr = Ms + i * KP;
            float r[10];
#pragma unroll
            for (int q = 0; q < 10; ++q) {
                int j = l + 32 * q;
                r[q] = (j < KP) ? mr[j] + Vs[j] : DEV_NEG_INF;
            }
            float m1 = vlast;
#pragma unroll
            for (int q = 0; q < 10; ++q) m1 = fmaxf(m1, r[q]);
            m1 = wred_max(m1);
            float s = (l == 0) ? __expf(vlast - m1) : 0.f;
#pragma unroll
            for (int q = 0; q < 10; ++q) s += __expf(r[q] - m1);
            s = wred_sum(s);
            if (l == 0) logu[i] = -(m1 + logf(s));
        }
        __syncthreads();

        // -------- Phase C: column (max,sumexp) partials (dual accum) -------
        int pw = it & 1;
        for (int j = tid; j < KP; j += STHREADS) {
            float ma = DEV_NEG_INF, mb = DEV_NEG_INF;
            int i = 0;
            for (; i + 1 < rows; i += 2) {
                ma = fmaxf(ma, Ms[i * KP + j] + logu[i]);
                mb = fmaxf(mb, Ms[(i + 1) * KP + j] + logu[i + 1]);
            }
            if (i < rows) ma = fmaxf(ma, Ms[i * KP + j] + logu[i]);
            float m1 = fmaxf(ma, mb);
            float sa = 0.f, sb = 0.f;
            i = 0;
            for (; i + 1 < rows; i += 2) {
                sa += __expf(Ms[i * KP + j] + logu[i] - m1);
                sb += __expf(Ms[(i + 1) * KP + j] + logu[i + 1] - m1);
            }
            if (i < rows) sa += __expf(Ms[i * KP + j] + logu[i] - m1);
            __stcg(&g_cpart[pw][(t * KP + j) * 8 + sub], make_float2(m1, sa + sb));
        }
        if (tid < 32) {
            float m1 = DEV_NEG_INF;
            for (int i = l; i < rows; i += 32) m1 = fmaxf(m1, logu[i]);
            m1 = wred_max(m1);
            float s = 0.f;
            for (int i = l; i < rows; i += 32) s += __expf(logu[i] - m1);
            s = wred_sum(s);
            if (l == 0) __stcg(&g_upart[pw][c], make_float2(m1, s));
        }
        grid_barrier(it);
    }

    // -------- Epilogue: T nonzeros + logits --------------------------------
    for (int i = w; i < rows; i += STHREADS / 32) {
        int n = g_perm[r0 + i];
        float lu = logu[i];
        const float* mr = Ms + i * KP;
        float* Trow = out_T + (size_t)n * NSLOT + t;
        float* Lrow = out_logits + (size_t)n * KP;
#pragma unroll
        for (int q = 0; q < 10; ++q) {
            int j = l + 32 * q;
            if (j < KP) {
                float val = __expf(mr[j] + lu + Vs[j]);
                Trow[j * NT] = val;
                Lrow[j] = logf(val + 1e-8f);
            }
        }
    }
}

// ---------------- launch ----------------------------------------------------
extern "C" void kernel_launch(void* const* d_in, const int* in_sizes, int n_in,
                              void* d_out, int out_size)
{
    const float* emb   = (const float*)d_in[0];
    const float* W1    = (const float*)d_in[1];
    const float* b1    = (const float*)d_in[2];
    const float* proto = (const float*)d_in[3];
    const int*   jt    = (const int*)d_in[4];
    (void)in_sizes; (void)n_in; (void)out_size;

    float* logits = (float*)d_out;
    float* T      = logits + (size_t)Nn * KP;

    size_t smem = (size_t)(ROWCAP * KP + KP + 4 + ROWCAP + 8) * sizeof(float);
    cudaFuncSetAttribute(sinkhorn_kernel,
                         cudaFuncAttributeMaxDynamicSharedMemorySize, (int)smem);

    gemm_h_kernel<<<dim3(Dd / 128, Nn / 128), 256>>>(emb, W1, b1);
    normsort_kernel<<<Nn / 8 + 49, 256>>>(proto, jt);
    gemm_M_kernel<<<dim3(3, Nn / 128), 256>>>(proto);
    cudaMemsetAsync(T, 0, (size_t)Nn * NSLOT * sizeof(float));
    sinkhorn_kernel<<<NCTA, STHREADS, smem>>>(logits, T);
}